// round 1
// baseline (speedup 1.0000x reference)
#include <cuda_runtime.h>
#include <cuda_bf16.h>
#include <math.h>

// Problem constants
#define B_      2
#define CIN     48
#define HH      512
#define WW      512
#define HW      (512*512)
#define CQ      144      // 3*DIM
#define HEADS   8
#define CSUB    6        // DIM/HEADS
#define NB      4
#define H1      128
#define NTOK    16384    // H1*W1
#define CB      96       // CSUB*NB*NB
#define NCHUNK  16       // split-K chunks for gram
#define BHTOT   16       // B*HEADS

// ---------------- scratch (device globals; no allocations allowed) ----------------
__device__ float g_qkv[(size_t)B_*CQ*HW];              // after 1x1 conv
__device__ float g_q [(size_t)BHTOT*CB*NTOK];          // after dw, block layout
__device__ float g_k [(size_t)BHTOT*CB*NTOK];
__device__ float g_v [(size_t)BHTOT*CB*NTOK];
__device__ float g_Spart[(size_t)BHTOT*NCHUNK*CB*CB];  // split-K gram partials
__device__ float g_ssqpart[2*BHTOT*NCHUNK*CB];         // row sum-sq partials (q then k)
__device__ float g_attn[(size_t)BHTOT*CB*CB];          // softmaxed attention
__device__ float g_out1[(size_t)B_*CIN*HW];            // attn output, NCHW

// ---------------- K1: 1x1 conv qkv  (GEMM [144x48] @ [48 x HW]) ----------------
// grid (HW/256, 3, B), block 256. Thread computes 6 oc x 8 px.
__global__ void k_qkv(const float* __restrict__ x, const float* __restrict__ wq) {
    __shared__ float Xs[24][256];
    __shared__ float Wsh[48][48];
    const int b   = blockIdx.z;
    const int oc0 = blockIdx.y * 48;
    const int px0 = blockIdx.x * 256;
    const int tid = threadIdx.x;
    const int lane = tid & 31;
    const int wgrp = tid >> 5;        // 0..7  -> oc group of 6

    for (int i = tid; i < 48*48; i += 256) {
        int oc = i / 48, ic = i % 48;
        Wsh[oc][ic] = wq[(oc0 + oc)*48 + ic];
    }
    const float* xb = x + (size_t)b*CIN*HW;
    float acc[6][8];
#pragma unroll
    for (int i = 0; i < 6; ++i)
#pragma unroll
        for (int j = 0; j < 8; ++j) acc[i][j] = 0.f;

    for (int kc = 0; kc < 2; ++kc) {
        __syncthreads();
        for (int i = tid; i < 24*256; i += 256) {
            int ic = i >> 8, p = i & 255;
            Xs[ic][p] = xb[(size_t)(kc*24 + ic)*HW + px0 + p];
        }
        __syncthreads();
#pragma unroll
        for (int k = 0; k < 24; ++k) {
            float bv[8];
#pragma unroll
            for (int j = 0; j < 8; ++j) bv[j] = Xs[k][lane + 32*j];
#pragma unroll
            for (int i = 0; i < 6; ++i) {
                float a = Wsh[wgrp*6 + i][kc*24 + k];
#pragma unroll
                for (int j = 0; j < 8; ++j) acc[i][j] = fmaf(a, bv[j], acc[i][j]);
            }
        }
    }
    float* outb = g_qkv + (size_t)b*CQ*HW;
#pragma unroll
    for (int i = 0; i < 6; ++i) {
        int oc = oc0 + wgrp*6 + i;
#pragma unroll
        for (int j = 0; j < 8; ++j)
            outb[(size_t)oc*HW + px0 + lane + 32*j] = acc[i][j];
    }
}

// ---------------- K2: 3x3 depthwise (zero pad) + scatter into block layout ----------------
// grid (16,16,B*CQ), block 256
__global__ void k_dw(const float* __restrict__ dw) {
    __shared__ float tile[34][34];
    const int ch = blockIdx.z % CQ;
    const int b  = blockIdx.z / CQ;
    const int y0 = blockIdx.y * 32;
    const int x0 = blockIdx.x * 32;
    const int tid = threadIdx.x;

    const float* src = g_qkv + ((size_t)b*CQ + ch)*HW;
    for (int i = tid; i < 34*34; i += 256) {
        int yy = i / 34 - 1 + y0;
        int xx = i % 34 - 1 + x0;
        float v = 0.f;
        if (yy >= 0 && yy < HH && xx >= 0 && xx < WW) v = src[yy*WW + xx];
        tile[i/34][i%34] = v;
    }
    float w[9];
#pragma unroll
    for (int t = 0; t < 9; ++t) w[t] = dw[ch*9 + t];
    __syncthreads();

    const int part = ch / 48;            // 0=q 1=k 2=v
    const int chh  = ch % 48;
    const int head = chh / CSUB;
    const int ci   = chh % CSUB;
    float* base = (part == 0) ? g_q : (part == 1) ? g_k : g_v;
    float* dst = base + (size_t)(b*HEADS + head)*CB*NTOK;

    for (int p = tid; p < 1024; p += 256) {
        int ly = p >> 5, lx = p & 31;
        float s = 0.f;
#pragma unroll
        for (int dy = 0; dy < 3; ++dy)
#pragma unroll
            for (int dx = 0; dx < 3; ++dx)
                s = fmaf(w[dy*3 + dx], tile[ly + dy][lx + dx], s);
        int y = y0 + ly, xg = x0 + lx;
        int row = ci*16 + (y & 3)*4 + (xg & 3);
        int n   = (y >> 2)*H1 + (xg >> 2);
        dst[(size_t)row*NTOK + n] = s;
    }
}

// ---------------- K3: split-K gram S = q k^T + row sumsq partials ----------------
// grid (NCHUNK, BHTOT), block 256. Thread computes 6x6 of the 96x96 tile.
__global__ void k_gram() {
    __shared__ float Qs[96][33];
    __shared__ float Ks[96][33];
    const int chunk = blockIdx.x;
    const int bh    = blockIdx.y;
    const int tid = threadIdx.x;
    const int lane = tid & 31;
    const int w    = tid >> 5;
    const int rowg = tid >> 4;   // 0..15
    const int colg = tid & 15;   // 0..15
    const int n0 = chunk * (NTOK / NCHUNK);

    const float* Q  = g_q + (size_t)bh*CB*NTOK;
    const float* Kp = g_k + (size_t)bh*CB*NTOK;

    float acc[6][6];
#pragma unroll
    for (int i = 0; i < 6; ++i)
#pragma unroll
        for (int j = 0; j < 6; ++j) acc[i][j] = 0.f;
    float sq[12], sk[12];
#pragma unroll
    for (int t = 0; t < 12; ++t) { sq[t] = 0.f; sk[t] = 0.f; }

    for (int kt = 0; kt < (NTOK / NCHUNK) / 32; ++kt) {
        int base = n0 + kt*32;
#pragma unroll
        for (int t = 0; t < 12; ++t) {
            int i = tid + t*256;
            int r = i >> 5, c = i & 31;      // c == lane, r = w + 8t
            float qv = Q [(size_t)r*NTOK + base + c];
            float kv = Kp[(size_t)r*NTOK + base + c];
            Qs[r][c] = qv; Ks[r][c] = kv;
            sq[t] = fmaf(qv, qv, sq[t]);
            sk[t] = fmaf(kv, kv, sk[t]);
        }
        __syncthreads();
#pragma unroll
        for (int k = 0; k < 32; ++k) {
            float a[6], bv[6];
#pragma unroll
            for (int i = 0; i < 6; ++i) a[i]  = Qs[rowg*6 + i][k];
#pragma unroll
            for (int j = 0; j < 6; ++j) bv[j] = Ks[colg*6 + j][k];
#pragma unroll
            for (int i = 0; i < 6; ++i)
#pragma unroll
                for (int j = 0; j < 6; ++j) acc[i][j] = fmaf(a[i], bv[j], acc[i][j]);
        }
        __syncthreads();
    }
    float* Sp = g_Spart + ((size_t)bh*NCHUNK + chunk)*CB*CB;
#pragma unroll
    for (int i = 0; i < 6; ++i)
#pragma unroll
        for (int j = 0; j < 6; ++j)
            Sp[(rowg*6 + i)*CB + colg*6 + j] = acc[i][j];

    // warp w fully owns rows r = w + 8t across all columns -> warp reduce, no races
#pragma unroll
    for (int t = 0; t < 12; ++t) {
        float s1 = sq[t], s2 = sk[t];
#pragma unroll
        for (int off = 16; off > 0; off >>= 1) {
            s1 += __shfl_xor_sync(0xffffffffu, s1, off);
            s2 += __shfl_xor_sync(0xffffffffu, s2, off);
        }
        if (lane == 0) {
            int r = w + 8*t;
            g_ssqpart[((0*BHTOT + bh)*NCHUNK + chunk)*CB + r] = s1;
            g_ssqpart[((1*BHTOT + bh)*NCHUNK + chunk)*CB + r] = s2;
        }
    }
}

// ---------------- K4: reduce partials, scale by 1/(|q||k|)*temp, softmax ----------------
// grid (BHTOT), block 256 (8 warps; warp per row, 12 rows each)
__global__ void k_soft(const float* __restrict__ temperature) {
    __shared__ float invq[96], invk[96];
    const int bh = blockIdx.x;
    const int head = bh & 7;
    const int tid = threadIdx.x;
    const int lane = tid & 31;
    const int w = tid >> 5;

    if (tid < 96) {
        float sumq = 0.f, sumk = 0.f;
        for (int c = 0; c < NCHUNK; ++c) {
            sumq += g_ssqpart[((0*BHTOT + bh)*NCHUNK + c)*CB + tid];
            sumk += g_ssqpart[((1*BHTOT + bh)*NCHUNK + c)*CB + tid];
        }
        invq[tid] = 1.f / fmaxf(sqrtf(sumq), 1e-12f);
        invk[tid] = 1.f / fmaxf(sqrtf(sumk), 1e-12f);
    }
    __syncthreads();
    const float temp = temperature[head];
    const float* Sp = g_Spart + (size_t)bh*NCHUNK*CB*CB;
    float* Ao = g_attn + (size_t)bh*CB*CB;

    for (int row = w; row < CB; row += 8) {
        float v[3];
#pragma unroll
        for (int j = 0; j < 3; ++j) {
            int col = lane + 32*j;
            float s = 0.f;
            for (int c = 0; c < NCHUNK; ++c) s += Sp[c*CB*CB + row*CB + col];
            v[j] = s * temp * invq[row] * invk[col];
        }
        float m = fmaxf(v[0], fmaxf(v[1], v[2]));
#pragma unroll
        for (int off = 16; off > 0; off >>= 1) m = fmaxf(m, __shfl_xor_sync(0xffffffffu, m, off));
        float e[3], sum = 0.f;
#pragma unroll
        for (int j = 0; j < 3; ++j) { e[j] = __expf(v[j] - m); sum += e[j]; }
#pragma unroll
        for (int off = 16; off > 0; off >>= 1) sum += __shfl_xor_sync(0xffffffffu, sum, off);
        float inv = 1.f / sum;
#pragma unroll
        for (int j = 0; j < 3; ++j) Ao[row*CB + lane + 32*j] = e[j] * inv;
    }
}

// ---------------- K5: out = attn @ v, fused from_blocks scatter ----------------
// grid (NTOK/128, BHTOT), block 256. Thread computes 6 rows x 8 cols.
__global__ void k_av() {
    __shared__ float As[CB*CB];      // 36.9 KB
    __shared__ float Vs[16][128];    //  8 KB
    const int nt = blockIdx.x;       // 0..127
    const int bh = blockIdx.y;
    const int b = bh >> 3, head = bh & 7;
    const int tid = threadIdx.x;
    const int rowg = tid >> 4, colg = tid & 15;

    const float* A = g_attn + (size_t)bh*CB*CB;
    for (int i = tid; i < CB*CB; i += 256) As[i] = A[i];

    const float* V = g_v + (size_t)bh*CB*NTOK + nt*128;
    float acc[6][8];
#pragma unroll
    for (int i = 0; i < 6; ++i)
#pragma unroll
        for (int j = 0; j < 8; ++j) acc[i][j] = 0.f;

    for (int kc = 0; kc < 6; ++kc) {
        __syncthreads();
        for (int i = tid; i < 16*128; i += 256) {
            int r = i >> 7, cc = i & 127;
            Vs[r][cc] = V[(size_t)(kc*16 + r)*NTOK + cc];
        }
        __syncthreads();
#pragma unroll
        for (int k = 0; k < 16; ++k) {
            float bv[8];
#pragma unroll
            for (int j = 0; j < 8; ++j) bv[j] = Vs[k][colg*8 + j];
#pragma unroll
            for (int i = 0; i < 6; ++i) {
                float a = As[(rowg*6 + i)*CB + kc*16 + k];
#pragma unroll
                for (int j = 0; j < 8; ++j) acc[i][j] = fmaf(a, bv[j], acc[i][j]);
            }
        }
    }
    float* outb = g_out1 + (size_t)b*CIN*HW;
#pragma unroll
    for (int i = 0; i < 6; ++i) {
        int r = rowg*6 + i;
        int ci = r >> 4, rem = r & 15, Nh = rem >> 2, Nw = rem & 3;
        int ch = head*CSUB + ci;
#pragma unroll
        for (int j = 0; j < 8; ++j) {
            int n = nt*128 + colg*8 + j;
            int h1 = n >> 7, w1 = n & 127;
            int y = h1*4 + Nh, xg = w1*4 + Nw;
            outb[((size_t)ch*HH + y)*WW + xg] = acc[i][j];
        }
    }
}

// ---------------- K6: 1x1 proj conv  (GEMM [48x48] @ [48 x HW]) ----------------
// grid (HW/256, 1, B), block 256
__global__ void k_proj(const float* __restrict__ wp, float* __restrict__ out) {
    __shared__ float Xs[24][256];
    __shared__ float Wsh[48][48];
    const int b   = blockIdx.z;
    const int px0 = blockIdx.x * 256;
    const int tid = threadIdx.x;
    const int lane = tid & 31;
    const int wgrp = tid >> 5;

    for (int i = tid; i < 48*48; i += 256) {
        int oc = i / 48, ic = i % 48;
        Wsh[oc][ic] = wp[oc*48 + ic];
    }
    const float* xb = g_out1 + (size_t)b*CIN*HW;
    float acc[6][8];
#pragma unroll
    for (int i = 0; i < 6; ++i)
#pragma unroll
        for (int j = 0; j < 8; ++j) acc[i][j] = 0.f;

    for (int kc = 0; kc < 2; ++kc) {
        __syncthreads();
        for (int i = tid; i < 24*256; i += 256) {
            int ic = i >> 8, p = i & 255;
            Xs[ic][p] = xb[(size_t)(kc*24 + ic)*HW + px0 + p];
        }
        __syncthreads();
#pragma unroll
        for (int k = 0; k < 24; ++k) {
            float bv[8];
#pragma unroll
            for (int j = 0; j < 8; ++j) bv[j] = Xs[k][lane + 32*j];
#pragma unroll
            for (int i = 0; i < 6; ++i) {
                float a = Wsh[wgrp*6 + i][kc*24 + k];
#pragma unroll
                for (int j = 0; j < 8; ++j) acc[i][j] = fmaf(a, bv[j], acc[i][j]);
            }
        }
    }
    float* ob = out + (size_t)b*CIN*HW;
#pragma unroll
    for (int i = 0; i < 6; ++i) {
        int oc = wgrp*6 + i;
#pragma unroll
        for (int j = 0; j < 8; ++j)
            ob[(size_t)oc*HW + px0 + lane + 32*j] = acc[i][j];
    }
}

// ---------------- launch ----------------
extern "C" void kernel_launch(void* const* d_in, const int* in_sizes, int n_in,
                              void* d_out, int out_size) {
    (void)in_sizes; (void)n_in; (void)out_size;
    const float* x      = (const float*)d_in[0];
    const float* qkv_w  = (const float*)d_in[1];
    const float* dw_w   = (const float*)d_in[2];
    const float* proj_w = (const float*)d_in[3];
    const float* temper = (const float*)d_in[4];
    float* out = (float*)d_out;

    k_qkv <<<dim3(HW/256, 3, B_), 256>>>(x, qkv_w);
    k_dw  <<<dim3(16, 16, B_*CQ), 256>>>(dw_w);
    k_gram<<<dim3(NCHUNK, BHTOT), 256>>>();
    k_soft<<<BHTOT, 256>>>(temper);
    k_av  <<<dim3(NTOK/128, BHTOT), 256>>>();
    k_proj<<<dim3(HW/256, 1, B_), 256>>>(proj_w, out);
}

// round 2
// speedup vs baseline: 1.0901x; 1.0901x over previous
#include <cuda_runtime.h>
#include <cuda_bf16.h>
#include <math.h>

// Problem constants
#define B_      2
#define CIN     48
#define HH      512
#define WW      512
#define HW      (512*512)
#define CQ      144      // 3*DIM
#define HEADS   8
#define CSUB    6        // DIM/HEADS
#define NB      4
#define H1      128
#define NTOK    16384    // H1*W1
#define CB      96       // CSUB*NB*NB
#define NCHUNK  16       // split-K chunks for gram
#define BHTOT   16       // B*HEADS

// ---------------- scratch (device globals; no allocations allowed) ----------------
__device__ float g_qkv[(size_t)B_*CQ*HW];              // after 1x1 conv
__device__ float g_q [(size_t)BHTOT*CB*NTOK];          // after dw, block layout
__device__ float g_k [(size_t)BHTOT*CB*NTOK];
__device__ float g_v [(size_t)BHTOT*CB*NTOK];
__device__ float g_Spart[(size_t)BHTOT*NCHUNK*CB*CB];  // split-K gram partials
__device__ float g_ssqpart[2*BHTOT*NCHUNK*CB];         // row sum-sq partials (q then k)
__device__ float g_attn[(size_t)BHTOT*CB*CB];          // softmaxed attention
__device__ float g_out1[(size_t)B_*CIN*HW];            // attn output, NCHW

// ---------------- K1: 1x1 conv qkv  (GEMM [144x48] @ [48 x HW]) ----------------
// grid (HW/256, 2, B), block 256. Each warp-group computes 9 oc x 8 px; block covers 72 oc.
__global__ void __launch_bounds__(256, 2) k_qkv(const float* __restrict__ x, const float* __restrict__ wq) {
    __shared__ float Xs[24][256];
    __shared__ float Wsh[72][48];
    const int b   = blockIdx.z;
    const int oc0 = blockIdx.y * 72;
    const int px0 = blockIdx.x * 256;
    const int tid = threadIdx.x;
    const int lane = tid & 31;
    const int wgrp = tid >> 5;        // 0..7 -> oc group of 9

    for (int i = tid; i < 72*48; i += 256) {
        int oc = i / 48, ic = i % 48;
        Wsh[oc][ic] = wq[(oc0 + oc)*48 + ic];
    }
    const float* xb = x + (size_t)b*CIN*HW;
    float acc[9][8];
#pragma unroll
    for (int i = 0; i < 9; ++i)
#pragma unroll
        for (int j = 0; j < 8; ++j) acc[i][j] = 0.f;

    for (int kc = 0; kc < 2; ++kc) {
        __syncthreads();
        for (int i = tid; i < 24*256; i += 256) {
            int ic = i >> 8, p = i & 255;
            Xs[ic][p] = xb[(size_t)(kc*24 + ic)*HW + px0 + p];
        }
        __syncthreads();
#pragma unroll
        for (int k = 0; k < 24; ++k) {
            float bv[8];
#pragma unroll
            for (int j = 0; j < 8; ++j) bv[j] = Xs[k][lane + 32*j];
#pragma unroll
            for (int i = 0; i < 9; ++i) {
                float a = Wsh[wgrp*9 + i][kc*24 + k];
#pragma unroll
                for (int j = 0; j < 8; ++j) acc[i][j] = fmaf(a, bv[j], acc[i][j]);
            }
        }
    }
    float* outb = g_qkv + (size_t)b*CQ*HW;
#pragma unroll
    for (int i = 0; i < 9; ++i) {
        int oc = oc0 + wgrp*9 + i;
#pragma unroll
        for (int j = 0; j < 8; ++j)
            outb[(size_t)oc*HW + px0 + lane + 32*j] = acc[i][j];
    }
}

// ---------------- K2: 3x3 depthwise (zero pad) + scatter into block layout ----------------
// grid (16,16,B*CQ), block 256
__global__ void k_dw(const float* __restrict__ dw) {
    __shared__ float tile[34][34];
    const int ch = blockIdx.z % CQ;
    const int b  = blockIdx.z / CQ;
    const int y0 = blockIdx.y * 32;
    const int x0 = blockIdx.x * 32;
    const int tid = threadIdx.x;

    const float* src = g_qkv + ((size_t)b*CQ + ch)*HW;
    for (int i = tid; i < 34*34; i += 256) {
        int yy = i / 34 - 1 + y0;
        int xx = i % 34 - 1 + x0;
        float v = 0.f;
        if (yy >= 0 && yy < HH && xx >= 0 && xx < WW) v = src[yy*WW + xx];
        tile[i/34][i%34] = v;
    }
    float w[9];
#pragma unroll
    for (int t = 0; t < 9; ++t) w[t] = dw[ch*9 + t];
    __syncthreads();

    const int part = ch / 48;            // 0=q 1=k 2=v
    const int chh  = ch % 48;
    const int head = chh / CSUB;
    const int ci   = chh % CSUB;
    float* base = (part == 0) ? g_q : (part == 1) ? g_k : g_v;
    float* dst = base + (size_t)(b*HEADS + head)*CB*NTOK;

    for (int p = tid; p < 1024; p += 256) {
        int ly = p >> 5, lx = p & 31;
        float s = 0.f;
#pragma unroll
        for (int dy = 0; dy < 3; ++dy)
#pragma unroll
            for (int dx = 0; dx < 3; ++dx)
                s = fmaf(w[dy*3 + dx], tile[ly + dy][lx + dx], s);
        int y = y0 + ly, xg = x0 + lx;
        int row = ci*16 + (y & 3)*4 + (xg & 3);
        int n   = (y >> 2)*H1 + (xg >> 2);
        dst[(size_t)row*NTOK + n] = s;
    }
}

// ---------------- K3: split-K gram S = q k^T + row sumsq partials ----------------
// grid (NCHUNK, BHTOT), block 256. Thread computes 6x6 of the 96x96 tile.
// smem tiles stored transposed [k][row] (pad 98) so fragments load as LDS.64.
__global__ void __launch_bounds__(256, 2) k_gram() {
    __shared__ float Qs[32][98];
    __shared__ float Ks[32][98];
    const int chunk = blockIdx.x;
    const int bh    = blockIdx.y;
    const int tid = threadIdx.x;
    const int lane = tid & 31;
    const int w    = tid >> 5;
    const int rowg = tid >> 4;   // 0..15
    const int colg = tid & 15;   // 0..15
    const int n0 = chunk * (NTOK / NCHUNK);

    const float* Q  = g_q + (size_t)bh*CB*NTOK;
    const float* Kp = g_k + (size_t)bh*CB*NTOK;

    float acc[6][6];
#pragma unroll
    for (int i = 0; i < 6; ++i)
#pragma unroll
        for (int j = 0; j < 6; ++j) acc[i][j] = 0.f;
    float sq[12], sk[12];
#pragma unroll
    for (int t = 0; t < 12; ++t) { sq[t] = 0.f; sk[t] = 0.f; }

    for (int kt = 0; kt < (NTOK / NCHUNK) / 32; ++kt) {
        int base = n0 + kt*32;
#pragma unroll
        for (int t = 0; t < 12; ++t) {
            int i = tid + t*256;
            int r = i >> 5, c = i & 31;      // c == lane, r = w + 8t
            float qv = Q [(size_t)r*NTOK + base + c];
            float kv = Kp[(size_t)r*NTOK + base + c];
            Qs[c][r] = qv; Ks[c][r] = kv;
            sq[t] = fmaf(qv, qv, sq[t]);
            sk[t] = fmaf(kv, kv, sk[t]);
        }
        __syncthreads();
#pragma unroll
        for (int k = 0; k < 32; ++k) {
            float a[6], bv[6];
            const float2* ap = (const float2*)&Qs[k][rowg*6];
            const float2* bp = (const float2*)&Ks[k][colg*6];
            float2 t0 = ap[0], t1 = ap[1], t2 = ap[2];
            a[0]=t0.x; a[1]=t0.y; a[2]=t1.x; a[3]=t1.y; a[4]=t2.x; a[5]=t2.y;
            float2 u0 = bp[0], u1 = bp[1], u2 = bp[2];
            bv[0]=u0.x; bv[1]=u0.y; bv[2]=u1.x; bv[3]=u1.y; bv[4]=u2.x; bv[5]=u2.y;
#pragma unroll
            for (int i = 0; i < 6; ++i)
#pragma unroll
                for (int j = 0; j < 6; ++j) acc[i][j] = fmaf(a[i], bv[j], acc[i][j]);
        }
        __syncthreads();
    }
    float* Sp = g_Spart + ((size_t)bh*NCHUNK + chunk)*CB*CB;
#pragma unroll
    for (int i = 0; i < 6; ++i)
#pragma unroll
        for (int j = 0; j < 6; ++j)
            Sp[(rowg*6 + i)*CB + colg*6 + j] = acc[i][j];

    // warp w fully owns rows r = w + 8t across all columns -> warp reduce, no races
#pragma unroll
    for (int t = 0; t < 12; ++t) {
        float s1 = sq[t], s2 = sk[t];
#pragma unroll
        for (int off = 16; off > 0; off >>= 1) {
            s1 += __shfl_xor_sync(0xffffffffu, s1, off);
            s2 += __shfl_xor_sync(0xffffffffu, s2, off);
        }
        if (lane == 0) {
            int r = w + 8*t;
            g_ssqpart[((0*BHTOT + bh)*NCHUNK + chunk)*CB + r] = s1;
            g_ssqpart[((1*BHTOT + bh)*NCHUNK + chunk)*CB + r] = s2;
        }
    }
}

// ---------------- K4: reduce partials, scale by 1/(|q||k|)*temp, softmax ----------------
// grid (12, BHTOT), block 256 (8 warps; warp per row, 8 rows per block)
__global__ void k_soft(const float* __restrict__ temperature) {
    __shared__ float invk[96];
    __shared__ float invq[8];
    const int bh = blockIdx.y;
    const int rb = blockIdx.x * 8;
    const int head = bh & 7;
    const int tid = threadIdx.x;
    const int lane = tid & 31;
    const int w = tid >> 5;

    if (tid < 96) {
        float sumk = 0.f;
        for (int c = 0; c < NCHUNK; ++c)
            sumk += g_ssqpart[((1*BHTOT + bh)*NCHUNK + c)*CB + tid];
        invk[tid] = 1.f / fmaxf(sqrtf(sumk), 1e-12f);
    } else if (tid >= 128 && tid < 136) {
        int r = rb + tid - 128;
        float sumq = 0.f;
        for (int c = 0; c < NCHUNK; ++c)
            sumq += g_ssqpart[((0*BHTOT + bh)*NCHUNK + c)*CB + r];
        invq[tid - 128] = 1.f / fmaxf(sqrtf(sumq), 1e-12f);
    }
    __syncthreads();
    const float temp = temperature[head];
    const float* Sp = g_Spart + (size_t)bh*NCHUNK*CB*CB;
    float* Ao = g_attn + (size_t)bh*CB*CB;

    const int row = rb + w;
    float v[3];
#pragma unroll
    for (int j = 0; j < 3; ++j) {
        int col = lane + 32*j;
        float s = 0.f;
        for (int c = 0; c < NCHUNK; ++c) s += Sp[c*CB*CB + row*CB + col];
        v[j] = s * temp * invq[w] * invk[col];
    }
    float m = fmaxf(v[0], fmaxf(v[1], v[2]));
#pragma unroll
    for (int off = 16; off > 0; off >>= 1) m = fmaxf(m, __shfl_xor_sync(0xffffffffu, m, off));
    float e[3], sum = 0.f;
#pragma unroll
    for (int j = 0; j < 3; ++j) { e[j] = __expf(v[j] - m); sum += e[j]; }
#pragma unroll
    for (int off = 16; off > 0; off >>= 1) sum += __shfl_xor_sync(0xffffffffu, sum, off);
    float inv = 1.f / sum;
#pragma unroll
    for (int j = 0; j < 3; ++j) Ao[row*CB + lane + 32*j] = e[j] * inv;
}

// ---------------- K5: out = attn @ v, fused from_blocks scatter (float4 writes) ----------------
// grid (128, BHTOT), block 384 (= 12 rowgroups x 32 token-lanes).
// Thread computes 8 rows (two complete Nw-quads) x 4 tokens (stride 32).
__global__ void __launch_bounds__(384, 2) k_av() {
    __shared__ float As[CB*CB];      // 36.9 KB
    __shared__ float Vs[16][128];    //  8 KB
    const int nt = blockIdx.x;       // 0..127  (== h1)
    const int bh = blockIdx.y;
    const int b = bh >> 3, head = bh & 7;
    const int tid = threadIdx.x;
    const int rg = tid >> 5;         // 0..11 : rows rg*8..rg*8+7
    const int tg = tid & 31;         // token lane

    const float* A = g_attn + (size_t)bh*CB*CB;
    for (int i = tid; i < CB*CB; i += 384) As[i] = A[i];

    const float* V = g_v + (size_t)bh*CB*NTOK + nt*128;
    float acc[8][4];
#pragma unroll
    for (int i = 0; i < 8; ++i)
#pragma unroll
        for (int j = 0; j < 4; ++j) acc[i][j] = 0.f;

    for (int kc = 0; kc < 6; ++kc) {
        __syncthreads();
        for (int i = tid; i < 16*128; i += 384) {
            int r = i >> 7, cc = i & 127;
            Vs[r][cc] = V[(size_t)(kc*16 + r)*NTOK + cc];
        }
        __syncthreads();
#pragma unroll
        for (int k = 0; k < 16; ++k) {
            float bv[4];
#pragma unroll
            for (int j = 0; j < 4; ++j) bv[j] = Vs[k][tg + 32*j];
#pragma unroll
            for (int i = 0; i < 8; ++i) {
                float a = As[(rg*8 + i)*CB + kc*16 + k];
#pragma unroll
                for (int j = 0; j < 4; ++j) acc[i][j] = fmaf(a, bv[j], acc[i][j]);
            }
        }
    }
    // rows r = rg*8 + i;  r = ci*16 + Nh*4 + Nw;  group = r>>2 = ci*4 + Nh
    float* outb = g_out1 + (size_t)b*CIN*HW;
#pragma unroll
    for (int g = 0; g < 2; ++g) {
        int group = rg*2 + g;
        int ci = group >> 2, Nh = group & 3;
        int ch = head*CSUB + ci;
        int y  = nt*4 + Nh;
#pragma unroll
        for (int j = 0; j < 4; ++j) {
            int w1 = tg + 32*j;
            float4 val = make_float4(acc[g*4+0][j], acc[g*4+1][j], acc[g*4+2][j], acc[g*4+3][j]);
            *(float4*)&outb[((size_t)ch*HH + y)*WW + w1*4] = val;
        }
    }
}

// ---------------- K6: 1x1 proj conv  (GEMM [48x48] @ [48 x HW]) ----------------
// grid (HW/256, 1, B), block 256
__global__ void k_proj(const float* __restrict__ wp, float* __restrict__ out) {
    __shared__ float Xs[24][256];
    __shared__ float Wsh[48][48];
    const int b   = blockIdx.z;
    const int px0 = blockIdx.x * 256;
    const int tid = threadIdx.x;
    const int lane = tid & 31;
    const int wgrp = tid >> 5;

    for (int i = tid; i < 48*48; i += 256) {
        int oc = i / 48, ic = i % 48;
        Wsh[oc][ic] = wp[oc*48 + ic];
    }
    const float* xb = g_out1 + (size_t)b*CIN*HW;
    float acc[6][8];
#pragma unroll
    for (int i = 0; i < 6; ++i)
#pragma unroll
        for (int j = 0; j < 8; ++j) acc[i][j] = 0.f;

    for (int kc = 0; kc < 2; ++kc) {
        __syncthreads();
        for (int i = tid; i < 24*256; i += 256) {
            int ic = i >> 8, p = i & 255;
            Xs[ic][p] = xb[(size_t)(kc*24 + ic)*HW + px0 + p];
        }
        __syncthreads();
#pragma unroll
        for (int k = 0; k < 24; ++k) {
            float bv[8];
#pragma unroll
            for (int j = 0; j < 8; ++j) bv[j] = Xs[k][lane + 32*j];
#pragma unroll
            for (int i = 0; i < 6; ++i) {
                float a = Wsh[wgrp*6 + i][kc*24 + k];
#pragma unroll
                for (int j = 0; j < 8; ++j) acc[i][j] = fmaf(a, bv[j], acc[i][j]);
            }
        }
    }
    float* ob = out + (size_t)b*CIN*HW;
#pragma unroll
    for (int i = 0; i < 6; ++i) {
        int oc = wgrp*6 + i;
#pragma unroll
        for (int j = 0; j < 8; ++j)
            ob[(size_t)oc*HW + px0 + lane + 32*j] = acc[i][j];
    }
}

// ---------------- launch ----------------
extern "C" void kernel_launch(void* const* d_in, const int* in_sizes, int n_in,
                              void* d_out, int out_size) {
    (void)in_sizes; (void)n_in; (void)out_size;
    const float* x      = (const float*)d_in[0];
    const float* qkv_w  = (const float*)d_in[1];
    const float* dw_w   = (const float*)d_in[2];
    const float* proj_w = (const float*)d_in[3];
    const float* temper = (const float*)d_in[4];
    float* out = (float*)d_out;

    k_qkv <<<dim3(HW/256, 2, B_), 256>>>(x, qkv_w);
    k_dw  <<<dim3(16, 16, B_*CQ), 256>>>(dw_w);
    k_gram<<<dim3(NCHUNK, BHTOT), 256>>>();
    k_soft<<<dim3(12, BHTOT), 256>>>(temper);
    k_av  <<<dim3(NTOK/128, BHTOT), 384>>>();
    k_proj<<<dim3(HW/256, 1, B_), 256>>>(proj_w, out);
}

// round 3
// speedup vs baseline: 1.1205x; 1.0279x over previous
#include <cuda_runtime.h>
#include <cuda_bf16.h>
#include <math.h>

// Problem constants
#define B_      2
#define CIN     48
#define HH      512
#define WW      512
#define HW      (512*512)
#define CQ      144      // 3*DIM
#define HEADS   8
#define CSUB    6        // DIM/HEADS
#define NB      4
#define H1      128
#define NTOK    16384    // H1*W1
#define CB      96       // CSUB*NB*NB
#define NCHUNK  16       // split-K chunks for gram
#define BHTOT   16       // B*HEADS

typedef unsigned long long u64;

// packed fp32x2 FMA: d = a*b + d (elementwise on 2 packed floats). Bitwise == 2x fmaf.
__device__ __forceinline__ void ffma2(u64& d, u64 a, u64 b) {
    asm("fma.rn.f32x2 %0, %1, %2, %0;" : "+l"(d) : "l"(a), "l"(b));
}
__device__ __forceinline__ u64 pack2(float lo, float hi) {
    u64 r; asm("mov.b64 %0, {%1, %2};" : "=l"(r) : "f"(lo), "f"(hi)); return r;
}
__device__ __forceinline__ float2 unpack2(u64 v) {
    float2 r; asm("mov.b64 {%0, %1}, %2;" : "=f"(r.x), "=f"(r.y) : "l"(v)); return r;
}

// ---------------- scratch (device globals; no allocations allowed) ----------------
__device__ float g_qkv[(size_t)B_*CQ*HW];              // after 1x1 conv
__device__ float g_q [(size_t)BHTOT*CB*NTOK];          // after dw, block layout
__device__ float g_k [(size_t)BHTOT*CB*NTOK];
__device__ float g_v [(size_t)BHTOT*CB*NTOK];
__device__ float g_Spart[(size_t)BHTOT*NCHUNK*CB*CB];  // split-K gram partials
__device__ float g_ssqpart[2*BHTOT*NCHUNK*CB];         // row sum-sq partials (q then k)
__device__ float g_attn[(size_t)BHTOT*CB*CB];          // softmaxed attention
__device__ float g_out1[(size_t)B_*CIN*HW];            // attn output, NCHW

// ---------------- K1: 1x1 conv qkv  (GEMM [144x48] @ [48 x HW]), f32x2 ----------------
// grid (HW/256, 2, B), block 256. Warp-group computes 9 oc x 4 pixel-pairs.
__global__ void __launch_bounds__(256, 2) k_qkv(const float* __restrict__ x, const float* __restrict__ wq) {
    __shared__ float Xs[24][256];     // 24 KB
    __shared__ u64   W2[72][48];      // 27.6 KB, weights duplicated (w,w)
    const int b   = blockIdx.z;
    const int oc0 = blockIdx.y * 72;
    const int px0 = blockIdx.x * 256;
    const int tid = threadIdx.x;
    const int lane = tid & 31;
    const int wgrp = tid >> 5;        // 0..7 -> oc group of 9

    for (int i = tid; i < 72*48; i += 256) {
        int oc = i / 48, ic = i % 48;
        float w = wq[(oc0 + oc)*48 + ic];
        W2[oc][ic] = pack2(w, w);
    }
    const float* xb = x + (size_t)b*CIN*HW;
    u64 acc[9][4];
#pragma unroll
    for (int i = 0; i < 9; ++i)
#pragma unroll
        for (int j = 0; j < 4; ++j) acc[i][j] = 0ull;

    for (int kc = 0; kc < 2; ++kc) {
        __syncthreads();
        for (int i = tid; i < 24*256; i += 256) {
            int ic = i >> 8, p = i & 255;
            Xs[ic][p] = xb[(size_t)(kc*24 + ic)*HW + px0 + p];
        }
        __syncthreads();
#pragma unroll
        for (int k = 0; k < 24; ++k) {
            u64 bv[4];
#pragma unroll
            for (int j = 0; j < 4; ++j) bv[j] = *(const u64*)&Xs[k][2*lane + 64*j];
#pragma unroll
            for (int i = 0; i < 9; ++i) {
                u64 a2 = W2[wgrp*9 + i][kc*24 + k];
#pragma unroll
                for (int j = 0; j < 4; ++j) ffma2(acc[i][j], a2, bv[j]);
            }
        }
    }
    float* outb = g_qkv + (size_t)b*CQ*HW;
#pragma unroll
    for (int i = 0; i < 9; ++i) {
        int oc = oc0 + wgrp*9 + i;
#pragma unroll
        for (int j = 0; j < 4; ++j)
            *(float2*)&outb[(size_t)oc*HW + px0 + 2*lane + 64*j] = unpack2(acc[i][j]);
    }
}

// ---------------- K2: 3x3 depthwise (zero pad) + scatter into block layout ----------------
// grid (16,16,B*CQ), block 256
__global__ void k_dw(const float* __restrict__ dw) {
    __shared__ float tile[34][34];
    const int ch = blockIdx.z % CQ;
    const int b  = blockIdx.z / CQ;
    const int y0 = blockIdx.y * 32;
    const int x0 = blockIdx.x * 32;
    const int tid = threadIdx.x;

    const float* src = g_qkv + ((size_t)b*CQ + ch)*HW;
    for (int i = tid; i < 34*34; i += 256) {
        int yy = i / 34 - 1 + y0;
        int xx = i % 34 - 1 + x0;
        float v = 0.f;
        if (yy >= 0 && yy < HH && xx >= 0 && xx < WW) v = src[yy*WW + xx];
        tile[i/34][i%34] = v;
    }
    float w[9];
#pragma unroll
    for (int t = 0; t < 9; ++t) w[t] = dw[ch*9 + t];
    __syncthreads();

    const int part = ch / 48;            // 0=q 1=k 2=v
    const int chh  = ch % 48;
    const int head = chh / CSUB;
    const int ci   = chh % CSUB;
    float* base = (part == 0) ? g_q : (part == 1) ? g_k : g_v;
    float* dst = base + (size_t)(b*HEADS + head)*CB*NTOK;

    for (int p = tid; p < 1024; p += 256) {
        int ly = p >> 5, lx = p & 31;
        float s = 0.f;
#pragma unroll
        for (int dy = 0; dy < 3; ++dy)
#pragma unroll
            for (int dx = 0; dx < 3; ++dx)
                s = fmaf(w[dy*3 + dx], tile[ly + dy][lx + dx], s);
        int y = y0 + ly, xg = x0 + lx;
        int row = ci*16 + (y & 3)*4 + (xg & 3);
        int n   = (y >> 2)*H1 + (xg >> 2);
        dst[(size_t)row*NTOK + n] = s;
    }
}

// ---------------- K3: split-K gram S = q k^T + row sumsq partials, f32x2 ----------------
// grid (NCHUNK, BHTOT), block 256. Thread computes 6 rows x 3 col-pairs of 96x96 tile.
__global__ void __launch_bounds__(256, 2) k_gram() {
    __shared__ u64   Qd[32][97];   // q duplicated (v,v); pad 97 kills store conflicts. 24.25 KB
    __shared__ float Ks[32][98];   // 12.5 KB
    const int chunk = blockIdx.x;
    const int bh    = blockIdx.y;
    const int tid = threadIdx.x;
    const int lane = tid & 31;
    const int w    = tid >> 5;
    const int rowg = tid >> 4;   // 0..15
    const int colg = tid & 15;   // 0..15
    const int n0 = chunk * (NTOK / NCHUNK);

    const float* Q  = g_q + (size_t)bh*CB*NTOK;
    const float* Kp = g_k + (size_t)bh*CB*NTOK;

    u64 acc[6][3];
#pragma unroll
    for (int i = 0; i < 6; ++i)
#pragma unroll
        for (int j = 0; j < 3; ++j) acc[i][j] = 0ull;
    float sq[12], sk[12];
#pragma unroll
    for (int t = 0; t < 12; ++t) { sq[t] = 0.f; sk[t] = 0.f; }

    for (int kt = 0; kt < (NTOK / NCHUNK) / 32; ++kt) {
        int base = n0 + kt*32;
#pragma unroll
        for (int t = 0; t < 12; ++t) {
            int i = tid + t*256;
            int r = i >> 5, c = i & 31;      // c == lane, r = w + 8t
            float qv = Q [(size_t)r*NTOK + base + c];
            float kv = Kp[(size_t)r*NTOK + base + c];
            Qd[c][r] = pack2(qv, qv);
            Ks[c][r] = kv;
            sq[t] = fmaf(qv, qv, sq[t]);
            sk[t] = fmaf(kv, kv, sk[t]);
        }
        __syncthreads();
#pragma unroll
        for (int k = 0; k < 32; ++k) {
            u64 bv[3];
#pragma unroll
            for (int j = 0; j < 3; ++j) bv[j] = *(const u64*)&Ks[k][colg*6 + 2*j];
#pragma unroll
            for (int i = 0; i < 6; ++i) {
                u64 a2 = Qd[k][rowg*6 + i];
#pragma unroll
                for (int j = 0; j < 3; ++j) ffma2(acc[i][j], a2, bv[j]);
            }
        }
        __syncthreads();
    }
    float* Sp = g_Spart + ((size_t)bh*NCHUNK + chunk)*CB*CB;
#pragma unroll
    for (int i = 0; i < 6; ++i)
#pragma unroll
        for (int j = 0; j < 3; ++j)
            *(float2*)&Sp[(rowg*6 + i)*CB + colg*6 + 2*j] = unpack2(acc[i][j]);

    // warp w fully owns rows r = w + 8t across all columns -> warp reduce, no races
#pragma unroll
    for (int t = 0; t < 12; ++t) {
        float s1 = sq[t], s2 = sk[t];
#pragma unroll
        for (int off = 16; off > 0; off >>= 1) {
            s1 += __shfl_xor_sync(0xffffffffu, s1, off);
            s2 += __shfl_xor_sync(0xffffffffu, s2, off);
        }
        if (lane == 0) {
            int r = w + 8*t;
            g_ssqpart[((0*BHTOT + bh)*NCHUNK + chunk)*CB + r] = s1;
            g_ssqpart[((1*BHTOT + bh)*NCHUNK + chunk)*CB + r] = s2;
        }
    }
}

// ---------------- K4: reduce partials, scale by 1/(|q||k|)*temp, softmax ----------------
// grid (12, BHTOT), block 256 (8 warps; warp per row)
__global__ void k_soft(const float* __restrict__ temperature) {
    __shared__ float invk[96];
    __shared__ float invq[8];
    const int bh = blockIdx.y;
    const int rb = blockIdx.x * 8;
    const int head = bh & 7;
    const int tid = threadIdx.x;
    const int lane = tid & 31;
    const int w = tid >> 5;

    if (tid < 96) {
        float sumk = 0.f;
        for (int c = 0; c < NCHUNK; ++c)
            sumk += g_ssqpart[((1*BHTOT + bh)*NCHUNK + c)*CB + tid];
        invk[tid] = 1.f / fmaxf(sqrtf(sumk), 1e-12f);
    } else if (tid >= 128 && tid < 136) {
        int r = rb + tid - 128;
        float sumq = 0.f;
        for (int c = 0; c < NCHUNK; ++c)
            sumq += g_ssqpart[((0*BHTOT + bh)*NCHUNK + c)*CB + r];
        invq[tid - 128] = 1.f / fmaxf(sqrtf(sumq), 1e-12f);
    }
    __syncthreads();
    const float temp = temperature[head];
    const float* Sp = g_Spart + (size_t)bh*NCHUNK*CB*CB;
    float* Ao = g_attn + (size_t)bh*CB*CB;

    const int row = rb + w;
    float v[3];
#pragma unroll
    for (int j = 0; j < 3; ++j) {
        int col = lane + 32*j;
        float s = 0.f;
        for (int c = 0; c < NCHUNK; ++c) s += Sp[c*CB*CB + row*CB + col];
        v[j] = s * temp * invq[w] * invk[col];
    }
    float m = fmaxf(v[0], fmaxf(v[1], v[2]));
#pragma unroll
    for (int off = 16; off > 0; off >>= 1) m = fmaxf(m, __shfl_xor_sync(0xffffffffu, m, off));
    float e[3], sum = 0.f;
#pragma unroll
    for (int j = 0; j < 3; ++j) { e[j] = __expf(v[j] - m); sum += e[j]; }
#pragma unroll
    for (int off = 16; off > 0; off >>= 1) sum += __shfl_xor_sync(0xffffffffu, sum, off);
    float inv = 1.f / sum;
#pragma unroll
    for (int j = 0; j < 3; ++j) Ao[row*CB + lane + 32*j] = e[j] * inv;
}

// ---------------- K5: out = attn @ v, fused from_blocks scatter, f32x2 ----------------
// grid (128, BHTOT), block 384 (= 12 rowgroups x 32 token-lanes).
// Thread computes 8 rows x 2 token-pairs; stores 2x float4 per row-quad = 32B runs.
__global__ void __launch_bounds__(384, 2) k_av() {
    __shared__ u64   As2[CB*CB];     // attn duplicated (a,a): 73.7 KB
    __shared__ float Vs[16][128];    //  8 KB
    const int nt = blockIdx.x;       // 0..127  (== h1)
    const int bh = blockIdx.y;
    const int b = bh >> 3, head = bh & 7;
    const int tid = threadIdx.x;
    const int rg = tid >> 5;         // 0..11 : rows rg*8..rg*8+7
    const int tg = tid & 31;         // token-pair lane

    const float* A = g_attn + (size_t)bh*CB*CB;
    for (int i = tid; i < CB*CB; i += 384) {
        float a = A[i];
        As2[i] = pack2(a, a);
    }

    const float* V = g_v + (size_t)bh*CB*NTOK + nt*128;
    u64 acc[8][2];
#pragma unroll
    for (int i = 0; i < 8; ++i) { acc[i][0] = 0ull; acc[i][1] = 0ull; }

    for (int kc = 0; kc < 6; ++kc) {
        __syncthreads();
        for (int i = tid; i < 16*128; i += 384) {
            int r = i >> 7, cc = i & 127;
            Vs[r][cc] = V[(size_t)(kc*16 + r)*NTOK + cc];
        }
        __syncthreads();
#pragma unroll
        for (int k = 0; k < 16; ++k) {
            u64 bv0 = *(const u64*)&Vs[k][2*tg];
            u64 bv1 = *(const u64*)&Vs[k][2*tg + 64];
#pragma unroll
            for (int i = 0; i < 8; ++i) {
                u64 a2 = As2[(rg*8 + i)*CB + kc*16 + k];
                ffma2(acc[i][0], a2, bv0);
                ffma2(acc[i][1], a2, bv1);
            }
        }
    }
    // rows r = rg*8 + i;  r = ci*16 + Nh*4 + Nw;  row-quad group = r>>2 = ci*4 + Nh
    float* outb = g_out1 + (size_t)b*CIN*HW;
#pragma unroll
    for (int g = 0; g < 2; ++g) {
        int group = rg*2 + g;
        int ci = group >> 2, Nh = group & 3;
        int ch = head*CSUB + ci;
        int y  = nt*4 + Nh;
#pragma unroll
        for (int jp = 0; jp < 2; ++jp) {
            float2 p0 = unpack2(acc[g*4+0][jp]);
            float2 p1 = unpack2(acc[g*4+1][jp]);
            float2 p2 = unpack2(acc[g*4+2][jp]);
            float2 p3 = unpack2(acc[g*4+3][jp]);
            size_t base = ((size_t)ch*HH + y)*WW + (size_t)(2*tg + 64*jp)*4;
            *(float4*)&outb[base]     = make_float4(p0.x, p1.x, p2.x, p3.x); // w1 = 2tg+64jp
            *(float4*)&outb[base + 4] = make_float4(p0.y, p1.y, p2.y, p3.y); // w1+1
        }
    }
}

// ---------------- K6: 1x1 proj conv  (GEMM [48x48] @ [48 x HW]), f32x2 ----------------
// grid (HW/256, 1, B), block 256
__global__ void __launch_bounds__(256, 2) k_proj(const float* __restrict__ wp, float* __restrict__ out) {
    __shared__ float Xs[24][256];   // 24 KB
    __shared__ u64   W2[48][48];    // 18.4 KB
    const int b   = blockIdx.z;
    const int px0 = blockIdx.x * 256;
    const int tid = threadIdx.x;
    const int lane = tid & 31;
    const int wgrp = tid >> 5;

    for (int i = tid; i < 48*48; i += 256) {
        int oc = i / 48, ic = i % 48;
        float w = wp[oc*48 + ic];
        W2[oc][ic] = pack2(w, w);
    }
    const float* xb = g_out1 + (size_t)b*CIN*HW;
    u64 acc[6][4];
#pragma unroll
    for (int i = 0; i < 6; ++i)
#pragma unroll
        for (int j = 0; j < 4; ++j) acc[i][j] = 0ull;

    for (int kc = 0; kc < 2; ++kc) {
        __syncthreads();
        for (int i = tid; i < 24*256; i += 256) {
            int ic = i >> 8, p = i & 255;
            Xs[ic][p] = xb[(size_t)(kc*24 + ic)*HW + px0 + p];
        }
        __syncthreads();
#pragma unroll
        for (int k = 0; k < 24; ++k) {
            u64 bv[4];
#pragma unroll
            for (int j = 0; j < 4; ++j) bv[j] = *(const u64*)&Xs[k][2*lane + 64*j];
#pragma unroll
            for (int i = 0; i < 6; ++i) {
                u64 a2 = W2[wgrp*6 + i][kc*24 + k];
#pragma unroll
                for (int j = 0; j < 4; ++j) ffma2(acc[i][j], a2, bv[j]);
            }
        }
    }
    float* ob = out + (size_t)b*CIN*HW;
#pragma unroll
    for (int i = 0; i < 6; ++i) {
        int oc = wgrp*6 + i;
#pragma unroll
        for (int j = 0; j < 4; ++j)
            *(float2*)&ob[(size_t)oc*HW + px0 + 2*lane + 64*j] = unpack2(acc[i][j]);
    }
}

// ---------------- launch ----------------
extern "C" void kernel_launch(void* const* d_in, const int* in_sizes, int n_in,
                              void* d_out, int out_size) {
    (void)in_sizes; (void)n_in; (void)out_size;
    const float* x      = (const float*)d_in[0];
    const float* qkv_w  = (const float*)d_in[1];
    const float* dw_w   = (const float*)d_in[2];
    const float* proj_w = (const float*)d_in[3];
    const float* temper = (const float*)d_in[4];
    float* out = (float*)d_out;

    k_qkv <<<dim3(HW/256, 2, B_), 256>>>(x, qkv_w);
    k_dw  <<<dim3(16, 16, B_*CQ), 256>>>(dw_w);
    k_gram<<<dim3(NCHUNK, BHTOT), 256>>>();
    k_soft<<<dim3(12, BHTOT), 256>>>(temper);
    k_av  <<<dim3(NTOK/128, BHTOT), 384>>>();
    k_proj<<<dim3(HW/256, 1, B_), 256>>>(proj_w, out);
}

// round 4
// speedup vs baseline: 1.5292x; 1.3647x over previous
#include <cuda_runtime.h>
#include <cuda_bf16.h>
#include <math.h>

// Problem constants
#define B_      2
#define CIN     48
#define HH      512
#define WW      512
#define HW      (512*512)
#define CQ      144      // 3*DIM
#define HEADS   8
#define CSUB    6        // DIM/HEADS
#define NB      4
#define H1      128
#define NTOK    16384    // H1*W1
#define CB      96       // CSUB*NB*NB
#define NCHUNK  16       // split-K chunks for gram
#define BHTOT   16       // B*HEADS

typedef unsigned long long u64;

// packed fp32x2 FMA: d = a*b + d. Bitwise == 2x fmaf.
__device__ __forceinline__ void ffma2(u64& d, u64 a, u64 b) {
    asm("fma.rn.f32x2 %0, %1, %2, %0;" : "+l"(d) : "l"(a), "l"(b));
}
__device__ __forceinline__ u64 pack2(float lo, float hi) {
    u64 r; asm("mov.b64 %0, {%1, %2};" : "=l"(r) : "f"(lo), "f"(hi)); return r;
}
__device__ __forceinline__ float2 unpack2(u64 v) {
    float2 r; asm("mov.b64 {%0, %1}, %2;" : "=f"(r.x), "=f"(r.y) : "l"(v)); return r;
}
__device__ __forceinline__ void cp16(void* smem_ptr, const void* gptr) {
    unsigned s = (unsigned)__cvta_generic_to_shared(smem_ptr);
    asm volatile("cp.async.cg.shared.global [%0], [%1], 16;" :: "r"(s), "l"(gptr));
}
__device__ __forceinline__ void cp_wait_all() {
    asm volatile("cp.async.commit_group;\n\tcp.async.wait_group 0;" ::: "memory");
}

// ---------------- scratch (device globals; no allocations allowed) ----------------
__device__ float g_qkv[(size_t)B_*CQ*HW];              // after 1x1 conv
__device__ float g_q [(size_t)BHTOT*CB*NTOK];          // after dw, block layout
__device__ float g_k [(size_t)BHTOT*CB*NTOK];
__device__ float g_v [(size_t)BHTOT*CB*NTOK];
__device__ float g_Spart[(size_t)BHTOT*NCHUNK*CB*CB];  // split-K gram partials
__device__ float g_ssqpart[2*BHTOT*NCHUNK*CB];         // row sum-sq partials (q then k)
__device__ float g_attn[(size_t)BHTOT*CB*CB];          // softmaxed attention
__device__ float g_out1[(size_t)B_*CIN*HW];            // attn output, NCHW

// ---------------- K1: 1x1 conv qkv  (GEMM [144x48] @ [48 x HW]), f32x2 ----------------
// grid (3, HW/256, B): oc-third on x so sibling blocks (same px) are adjacent -> share x via L2.
// Whole 48-ic X tile preloaded via cp.async (one long-MLP phase), then pure compute.
__global__ void __launch_bounds__(256, 3) k_qkv(const float* __restrict__ x, const float* __restrict__ wq) {
    __shared__ __align__(16) float Xs[48][256];   // 48 KB
    __shared__ __align__(16) u64   W2[48][48];    // 18.4 KB, weights duplicated (w,w)
    const int b   = blockIdx.z;
    const int oc0 = blockIdx.x * 48;
    const int px0 = blockIdx.y * 256;
    const int tid = threadIdx.x;
    const int lane = tid & 31;
    const int wgrp = tid >> 5;        // 0..7 -> oc group of 6

    const float* xb = x + (size_t)b*CIN*HW + px0;
    for (int i = tid; i < 48*64; i += 256) {
        int row = i >> 6, c4 = (i & 63) * 4;
        cp16(&Xs[row][c4], xb + (size_t)row*HW + c4);
    }
    for (int i = tid; i < 48*48; i += 256) {
        int oc = i / 48, ic = i % 48;
        float w = wq[(oc0 + oc)*48 + ic];
        W2[oc][ic] = pack2(w, w);
    }
    cp_wait_all();
    __syncthreads();

    u64 acc[6][4];
#pragma unroll
    for (int i = 0; i < 6; ++i)
#pragma unroll
        for (int j = 0; j < 4; ++j) acc[i][j] = 0ull;

#pragma unroll 4
    for (int k2 = 0; k2 < 24; ++k2) {
        const int k = 2*k2;
        u64 bv0[4], bv1[4];
#pragma unroll
        for (int j = 0; j < 4; ++j) {
            bv0[j] = *(const u64*)&Xs[k  ][2*lane + 64*j];
            bv1[j] = *(const u64*)&Xs[k+1][2*lane + 64*j];
        }
#pragma unroll
        for (int i = 0; i < 6; ++i) {
            const u64* wp2 = (const u64*)&W2[wgrp*6 + i][k];  // LDS.128 pair, broadcast
            u64 a0 = wp2[0], a1 = wp2[1];
#pragma unroll
            for (int j = 0; j < 4; ++j) { ffma2(acc[i][j], a0, bv0[j]); ffma2(acc[i][j], a1, bv1[j]); }
        }
    }
    float* outb = g_qkv + (size_t)b*CQ*HW;
#pragma unroll
    for (int i = 0; i < 6; ++i) {
        int oc = oc0 + wgrp*6 + i;
#pragma unroll
        for (int j = 0; j < 4; ++j)
            *(float2*)&outb[(size_t)oc*HW + px0 + 2*lane + 64*j] = unpack2(acc[i][j]);
    }
}

// ---------------- K2: 3x3 depthwise (zero pad) + scatter into block layout ----------------
// grid (8,16,B*CQ), block 256; 64x32 tile (halo 66x34)
__global__ void k_dw(const float* __restrict__ dw) {
    __shared__ float tile[34][66];
    const int ch = blockIdx.z % CQ;
    const int b  = blockIdx.z / CQ;
    const int y0 = blockIdx.y * 32;
    const int x0 = blockIdx.x * 64;
    const int tid = threadIdx.x;

    const float* src = g_qkv + ((size_t)b*CQ + ch)*HW;
    for (int i = tid; i < 34*66; i += 256) {
        int yy = i / 66 - 1 + y0;
        int xx = i % 66 - 1 + x0;
        float v = 0.f;
        if (yy >= 0 && yy < HH && xx >= 0 && xx < WW) v = src[yy*WW + xx];
        tile[i/66][i%66] = v;
    }
    float w[9];
#pragma unroll
    for (int t = 0; t < 9; ++t) w[t] = dw[ch*9 + t];
    __syncthreads();

    const int part = ch / 48;            // 0=q 1=k 2=v
    const int chh  = ch % 48;
    const int head = chh / CSUB;
    const int ci   = chh % CSUB;
    float* base = (part == 0) ? g_q : (part == 1) ? g_k : g_v;
    float* dst = base + (size_t)(b*HEADS + head)*CB*NTOK;

    for (int p = tid; p < 64*32; p += 256) {
        int ly = p >> 6, lx = p & 63;
        float s = 0.f;
#pragma unroll
        for (int dy = 0; dy < 3; ++dy)
#pragma unroll
            for (int dx = 0; dx < 3; ++dx)
                s = fmaf(w[dy*3 + dx], tile[ly + dy][lx + dx], s);
        int y = y0 + ly, xg = x0 + lx;
        int row = ci*16 + (y & 3)*4 + (xg & 3);
        int n   = (y >> 2)*H1 + (xg >> 2);
        dst[(size_t)row*NTOK + n] = s;
    }
}

// ---------------- K3: split-K gram, f32x2, register-staged pipeline ----------------
// grid (NCHUNK, BHTOT), block 256. Thread computes 6 rows x 3 col-pairs of 96x96 tile.
__global__ void __launch_bounds__(256, 2) k_gram() {
    __shared__ __align__(16) u64   Qd[32][97];   // q duplicated (v,v)
    __shared__ float Ks[32][98];
    const int chunk = blockIdx.x;
    const int bh    = blockIdx.y;
    const int tid = threadIdx.x;
    const int lane = tid & 31;
    const int w    = tid >> 5;
    const int rowg = tid >> 4;   // 0..15
    const int colg = tid & 15;   // 0..15
    const int n0 = chunk * (NTOK / NCHUNK);

    const float* Q  = g_q + (size_t)bh*CB*NTOK;
    const float* Kp = g_k + (size_t)bh*CB*NTOK;

    u64 acc[6][3];
#pragma unroll
    for (int i = 0; i < 6; ++i)
#pragma unroll
        for (int j = 0; j < 3; ++j) acc[i][j] = 0ull;
    float sq[12], sk[12];
#pragma unroll
    for (int t = 0; t < 12; ++t) { sq[t] = 0.f; sk[t] = 0.f; }

    float qr[12], kr[12];
#pragma unroll
    for (int t = 0; t < 12; ++t) {          // preload iter 0
        int r = w + 8*t;
        qr[t] = Q [(size_t)r*NTOK + n0 + lane];
        kr[t] = Kp[(size_t)r*NTOK + n0 + lane];
    }

    const int NIT = (NTOK / NCHUNK) / 32;   // 32
    for (int kt = 0; kt < NIT; ++kt) {
        __syncthreads();                    // prev compute done reading smem
#pragma unroll
        for (int t = 0; t < 12; ++t) {
            int r = w + 8*t;
            Qd[lane][r] = pack2(qr[t], qr[t]);
            Ks[lane][r] = kr[t];
            sq[t] = fmaf(qr[t], qr[t], sq[t]);
            sk[t] = fmaf(kr[t], kr[t], sk[t]);
        }
        __syncthreads();
        if (kt + 1 < NIT) {                 // loads in flight during compute below
            int base = n0 + (kt + 1)*32 + lane;
#pragma unroll
            for (int t = 0; t < 12; ++t) {
                int r = w + 8*t;
                qr[t] = Q [(size_t)r*NTOK + base];
                kr[t] = Kp[(size_t)r*NTOK + base];
            }
        }
#pragma unroll
        for (int k = 0; k < 32; ++k) {
            u64 bv[3];
#pragma unroll
            for (int j = 0; j < 3; ++j) bv[j] = *(const u64*)&Ks[k][colg*6 + 2*j];
#pragma unroll
            for (int i = 0; i < 6; ++i) {
                u64 a2 = Qd[k][rowg*6 + i];
#pragma unroll
                for (int j = 0; j < 3; ++j) ffma2(acc[i][j], a2, bv[j]);
            }
        }
    }
    float* Sp = g_Spart + ((size_t)bh*NCHUNK + chunk)*CB*CB;
#pragma unroll
    for (int i = 0; i < 6; ++i)
#pragma unroll
        for (int j = 0; j < 3; ++j)
            *(float2*)&Sp[(rowg*6 + i)*CB + colg*6 + 2*j] = unpack2(acc[i][j]);

#pragma unroll
    for (int t = 0; t < 12; ++t) {
        float s1 = sq[t], s2 = sk[t];
#pragma unroll
        for (int off = 16; off > 0; off >>= 1) {
            s1 += __shfl_xor_sync(0xffffffffu, s1, off);
            s2 += __shfl_xor_sync(0xffffffffu, s2, off);
        }
        if (lane == 0) {
            int r = w + 8*t;
            g_ssqpart[((0*BHTOT + bh)*NCHUNK + chunk)*CB + r] = s1;
            g_ssqpart[((1*BHTOT + bh)*NCHUNK + chunk)*CB + r] = s2;
        }
    }
}

// ---------------- K4: reduce partials, scale by 1/(|q||k|)*temp, softmax ----------------
__global__ void k_soft(const float* __restrict__ temperature) {
    __shared__ float invk[96];
    __shared__ float invq[8];
    const int bh = blockIdx.y;
    const int rb = blockIdx.x * 8;
    const int head = bh & 7;
    const int tid = threadIdx.x;
    const int lane = tid & 31;
    const int w = tid >> 5;

    if (tid < 96) {
        float sumk = 0.f;
        for (int c = 0; c < NCHUNK; ++c)
            sumk += g_ssqpart[((1*BHTOT + bh)*NCHUNK + c)*CB + tid];
        invk[tid] = 1.f / fmaxf(sqrtf(sumk), 1e-12f);
    } else if (tid >= 128 && tid < 136) {
        int r = rb + tid - 128;
        float sumq = 0.f;
        for (int c = 0; c < NCHUNK; ++c)
            sumq += g_ssqpart[((0*BHTOT + bh)*NCHUNK + c)*CB + r];
        invq[tid - 128] = 1.f / fmaxf(sqrtf(sumq), 1e-12f);
    }
    __syncthreads();
    const float temp = temperature[head];
    const float* Sp = g_Spart + (size_t)bh*NCHUNK*CB*CB;
    float* Ao = g_attn + (size_t)bh*CB*CB;

    const int row = rb + w;
    float v[3];
#pragma unroll
    for (int j = 0; j < 3; ++j) {
        int col = lane + 32*j;
        float s = 0.f;
        for (int c = 0; c < NCHUNK; ++c) s += Sp[c*CB*CB + row*CB + col];
        v[j] = s * temp * invq[w] * invk[col];
    }
    float m = fmaxf(v[0], fmaxf(v[1], v[2]));
#pragma unroll
    for (int off = 16; off > 0; off >>= 1) m = fmaxf(m, __shfl_xor_sync(0xffffffffu, m, off));
    float e[3], sum = 0.f;
#pragma unroll
    for (int j = 0; j < 3; ++j) { e[j] = __expf(v[j] - m); sum += e[j]; }
#pragma unroll
    for (int off = 16; off > 0; off >>= 1) sum += __shfl_xor_sync(0xffffffffu, sum, off);
    float inv = 1.f / sum;
#pragma unroll
    for (int j = 0; j < 3; ++j) Ao[row*CB + lane + 32*j] = e[j] * inv;
}

// ---------------- K5: out = attn @ v, fused scatter, f32x2, pipelined ----------------
// grid (128, BHTOT), block 384. 8 iters of 12 k-rows; V staged through regs (1 float4/thread).
__global__ void __launch_bounds__(384, 2) k_av() {
    __shared__ __align__(16) u64   As2[CB*CB];     // attn duplicated: 73.7 KB
    __shared__ __align__(16) float Vs[12][128];    //  6 KB
    const int nt = blockIdx.x;       // 0..127  (== h1)
    const int bh = blockIdx.y;
    const int b = bh >> 3, head = bh & 7;
    const int tid = threadIdx.x;
    const int rg = tid >> 5;         // 0..11 : rows rg*8..rg*8+7
    const int tg = tid & 31;         // token-pair lane
    const int vrow = tid >> 5;       // 0..11
    const int vc4  = (tid & 31) * 4;

    const float* A = g_attn + (size_t)bh*CB*CB;
    for (int i = tid; i < CB*CB; i += 384) {
        float a = A[i];
        As2[i] = pack2(a, a);
    }

    const float* V = g_v + (size_t)bh*CB*NTOK + nt*128;
    u64 acc[8][2];
#pragma unroll
    for (int i = 0; i < 8; ++i) { acc[i][0] = 0ull; acc[i][1] = 0ull; }

    float4 stage = *(const float4*)&V[(size_t)vrow*NTOK + vc4];   // iter 0

    for (int kc = 0; kc < 8; ++kc) {
        __syncthreads();
        *(float4*)&Vs[vrow][vc4] = stage;
        __syncthreads();
        if (kc + 1 < 8)
            stage = *(const float4*)&V[(size_t)((kc+1)*12 + vrow)*NTOK + vc4];
#pragma unroll
        for (int k = 0; k < 12; ++k) {
            u64 bv0 = *(const u64*)&Vs[k][2*tg];
            u64 bv1 = *(const u64*)&Vs[k][2*tg + 64];
#pragma unroll
            for (int i = 0; i < 8; ++i) {
                u64 a2 = As2[(rg*8 + i)*CB + kc*12 + k];
                ffma2(acc[i][0], a2, bv0);
                ffma2(acc[i][1], a2, bv1);
            }
        }
    }
    float* outb = g_out1 + (size_t)b*CIN*HW;
#pragma unroll
    for (int g = 0; g < 2; ++g) {
        int group = rg*2 + g;
        int ci = group >> 2, Nh = group & 3;
        int ch = head*CSUB + ci;
        int y  = nt*4 + Nh;
#pragma unroll
        for (int jp = 0; jp < 2; ++jp) {
            float2 p0 = unpack2(acc[g*4+0][jp]);
            float2 p1 = unpack2(acc[g*4+1][jp]);
            float2 p2 = unpack2(acc[g*4+2][jp]);
            float2 p3 = unpack2(acc[g*4+3][jp]);
            size_t base = ((size_t)ch*HH + y)*WW + (size_t)(2*tg + 64*jp)*4;
            *(float4*)&outb[base]     = make_float4(p0.x, p1.x, p2.x, p3.x);
            *(float4*)&outb[base + 4] = make_float4(p0.y, p1.y, p2.y, p3.y);
        }
    }
}

// ---------------- K6: 1x1 proj conv  (GEMM [48x48] @ [48 x HW]), f32x2, preload-all ----------------
__global__ void __launch_bounds__(256, 3) k_proj(const float* __restrict__ wp, float* __restrict__ out) {
    __shared__ __align__(16) float Xs[48][256];   // 48 KB
    __shared__ __align__(16) u64   W2[48][48];    // 18.4 KB
    const int b   = blockIdx.z;
    const int px0 = blockIdx.x * 256;
    const int tid = threadIdx.x;
    const int lane = tid & 31;
    const int wgrp = tid >> 5;

    const float* xb = g_out1 + (size_t)b*CIN*HW + px0;
    for (int i = tid; i < 48*64; i += 256) {
        int row = i >> 6, c4 = (i & 63) * 4;
        cp16(&Xs[row][c4], xb + (size_t)row*HW + c4);
    }
    for (int i = tid; i < 48*48; i += 256) {
        int oc = i / 48, ic = i % 48;
        float w = wp[oc*48 + ic];
        W2[oc][ic] = pack2(w, w);
    }
    cp_wait_all();
    __syncthreads();

    u64 acc[6][4];
#pragma unroll
    for (int i = 0; i < 6; ++i)
#pragma unroll
        for (int j = 0; j < 4; ++j) acc[i][j] = 0ull;

#pragma unroll 4
    for (int k2 = 0; k2 < 24; ++k2) {
        const int k = 2*k2;
        u64 bv0[4], bv1[4];
#pragma unroll
        for (int j = 0; j < 4; ++j) {
            bv0[j] = *(const u64*)&Xs[k  ][2*lane + 64*j];
            bv1[j] = *(const u64*)&Xs[k+1][2*lane + 64*j];
        }
#pragma unroll
        for (int i = 0; i < 6; ++i) {
            const u64* wp2 = (const u64*)&W2[wgrp*6 + i][k];
            u64 a0 = wp2[0], a1 = wp2[1];
#pragma unroll
            for (int j = 0; j < 4; ++j) { ffma2(acc[i][j], a0, bv0[j]); ffma2(acc[i][j], a1, bv1[j]); }
        }
    }
    float* ob = out + (size_t)b*CIN*HW;
#pragma unroll
    for (int i = 0; i < 6; ++i) {
        int oc = wgrp*6 + i;
#pragma unroll
        for (int j = 0; j < 4; ++j)
            *(float2*)&ob[(size_t)oc*HW + px0 + 2*lane + 64*j] = unpack2(acc[i][j]);
    }
}

// ---------------- launch ----------------
extern "C" void kernel_launch(void* const* d_in, const int* in_sizes, int n_in,
                              void* d_out, int out_size) {
    (void)in_sizes; (void)n_in; (void)out_size;
    const float* x      = (const float*)d_in[0];
    const float* qkv_w  = (const float*)d_in[1];
    const float* dw_w   = (const float*)d_in[2];
    const float* proj_w = (const float*)d_in[3];
    const float* temper = (const float*)d_in[4];
    float* out = (float*)d_out;

    k_qkv <<<dim3(3, HW/256, B_), 256>>>(x, qkv_w);
    k_dw  <<<dim3(8, 16, B_*CQ), 256>>>(dw_w);
    k_gram<<<dim3(NCHUNK, BHTOT), 256>>>();
    k_soft<<<dim3(12, BHTOT), 256>>>(temper);
    k_av  <<<dim3(NTOK/128, BHTOT), 384>>>();
    k_proj<<<dim3(HW/256, 1, B_), 256>>>(proj_w, out);
}